// round 1
// baseline (speedup 1.0000x reference)
#include <cuda_runtime.h>

// Problem constants
#define BSZ 64
#define ICAPS 8192
#define NDIM 8
#define JCAPS 8
#define MDIM 16

#define CI 16                       // in-caps per chunk staged in smem
#define NCHUNKS (ICAPS / CI)        // 512
#define GRID 128
#define GLOOP (NCHUNKS / GRID)      // 4 chunks per block
#define THREADS 512

// Stage s accumulators: s1, s2, s3 each [B, J, M]
__device__ float g_s[3][BSZ * JCAPS * MDIM];

// Dynamic smem layout (floats):
//   Ws:  CI*1024          (W chunk, transposed to [ci][n][j][m])
//   xs:  BSZ*CI*NDIM      (= 64*128, x chunk, [b][ci*8+n])
//   vs:  BSZ*128          (cumulative v, [b][j*16+m])
#define SMEM_FLOATS (CI*1024 + BSZ*CI*NDIM + BSZ*128)
#define SMEM_BYTES  (SMEM_FLOATS * 4)

__global__ __launch_bounds__(THREADS, 1)
void route_kernel(const float* __restrict__ x, const float* __restrict__ W, int stage)
{
    extern __shared__ float sh[];
    float* Ws = sh;
    float* xs = sh + CI*1024;
    float* vs = xs + BSZ*CI*NDIM;

    const int tid = threadIdx.x;

    // ---- Prologue: vsum = sum_{st<stage} squash(g_s[st]) into shared vs ----
    {
        const int b = tid >> 3;        // 512 threads == 64*8 (b,j) pairs
        const int j = tid & 7;
        float acc[MDIM];
        #pragma unroll
        for (int m = 0; m < MDIM; m++) acc[m] = 0.0f;
        for (int st = 0; st < stage; ++st) {
            const float* sp = &g_s[st][(b * JCAPS + j) * MDIM];
            float sv[MDIM];
            float sn = 0.0f;
            #pragma unroll
            for (int m = 0; m < MDIM; m++) { sv[m] = sp[m]; sn = fmaf(sv[m], sv[m], sn); }
            const float scale = sqrtf(sn) / (1.0f + sn);   // == sn/((1+sn)*sqrt(sn))
            #pragma unroll
            for (int m = 0; m < MDIM; m++) acc[m] = fmaf(scale, sv[m], acc[m]);
        }
        #pragma unroll
        for (int m = 0; m < MDIM; m++) vs[(b * JCAPS + j) * MDIM + m] = acc[m];
    }
    __syncthreads();

    const int lane = tid & 31;
    const int w    = tid >> 5;     // warp 0..15
    const int jj   = lane >> 2;    // out-cap j  0..7
    const int mq   = lane & 3;     // m-quad     0..3 (m = mq*4 .. mq*4+3)
    const int b0   = w * 4;        // this warp owns batches b0..b0+3

    float vr[4][4];                // vsum slice per owned batch
    float sacc[4][4];              // s accumulator per owned batch
    #pragma unroll
    for (int bb = 0; bb < 4; bb++) {
        const float4 t = *reinterpret_cast<const float4*>(&vs[(b0 + bb) * 128 + jj * 16 + mq * 4]);
        vr[bb][0] = t.x; vr[bb][1] = t.y; vr[bb][2] = t.z; vr[bb][3] = t.w;
        sacc[bb][0] = sacc[bb][1] = sacc[bb][2] = sacc[bb][3] = 0.0f;
    }

    for (int g = 0; g < GLOOP; ++g) {
        const int ch = blockIdx.x + g * GRID;
        const int i0 = ch * CI;

        __syncthreads();   // previous chunk fully consumed before restage
        // Stage W chunk: global [i][j][n][m] -> shared [ci][n][j][m]
        for (int idx4 = tid; idx4 < CI * 1024 / 4; idx4 += THREADS) {
            const int idx = idx4 * 4;
            const float4 t = *reinterpret_cast<const float4*>(&W[(size_t)i0 * 1024 + idx]);
            const int ci = idx >> 10;
            const int r  = idx & 1023;
            const int j  = r >> 7;
            const int n  = (r >> 4) & 7;
            const int m  = r & 15;       // multiple of 4
            float* d = &Ws[ci * 1024 + n * 128 + j * 16 + m];
            d[0] = t.x; d[1] = t.y; d[2] = t.z; d[3] = t.w;
        }
        // Stage x chunk: x[b, i0..i0+CI, :] is 128 contiguous floats per b
        for (int idx4 = tid; idx4 < BSZ * CI * NDIM / 4; idx4 += THREADS) {
            const int b  = idx4 >> 5;          // 32 float4 per batch row
            const int kk = (idx4 & 31) * 4;
            *reinterpret_cast<float4*>(&xs[b * 128 + kk]) =
                *reinterpret_cast<const float4*>(&x[(size_t)b * (ICAPS * NDIM) + (size_t)i0 * NDIM + kk]);
        }
        __syncthreads();

        for (int ci = 0; ci < CI; ++ci) {
            // Per-lane W slice: W[i, jj, n, mq*4..+3], n=0..7  (conflict-free LDS.128)
            float wr[8][4];
            #pragma unroll
            for (int n = 0; n < 8; n++) {
                const float4 t = *reinterpret_cast<const float4*>(&Ws[ci * 1024 + n * 128 + jj * 16 + mq * 4]);
                wr[n][0] = t.x; wr[n][1] = t.y; wr[n][2] = t.z; wr[n][3] = t.w;
            }
            #pragma unroll
            for (int bb = 0; bb < 4; bb++) {
                const int b = b0 + bb;
                float xv[8];
                {
                    const float4 t0 = *reinterpret_cast<const float4*>(&xs[b * 128 + ci * 8]);
                    const float4 t1 = *reinterpret_cast<const float4*>(&xs[b * 128 + ci * 8 + 4]);
                    xv[0] = t0.x; xv[1] = t0.y; xv[2] = t0.z; xv[3] = t0.w;
                    xv[4] = t1.x; xv[5] = t1.y; xv[6] = t1.z; xv[7] = t1.w;
                }
                // u_hat for (b, i=i0+ci, jj, mq*4..+3)
                float uh[4] = {0.0f, 0.0f, 0.0f, 0.0f};
                #pragma unroll
                for (int n = 0; n < 8; n++) {
                    #pragma unroll
                    for (int k = 0; k < 4; k++) uh[k] = fmaf(wr[n][k], xv[n], uh[k]);
                }
                // routing logit: dot(vsum[b,jj,:], u_hat[b,i,jj,:]) over m
                float p = uh[0] * vr[bb][0];
                p = fmaf(uh[1], vr[bb][1], p);
                p = fmaf(uh[2], vr[bb][2], p);
                p = fmaf(uh[3], vr[bb][3], p);
                p += __shfl_xor_sync(0xffffffffu, p, 1);   // reduce over m-quads
                p += __shfl_xor_sync(0xffffffffu, p, 2);
                // softmax over j (lanes jj*4+mq; xor 4/8/16 spans j)
                float mx = p;
                mx = fmaxf(mx, __shfl_xor_sync(0xffffffffu, mx, 4));
                mx = fmaxf(mx, __shfl_xor_sync(0xffffffffu, mx, 8));
                mx = fmaxf(mx, __shfl_xor_sync(0xffffffffu, mx, 16));
                const float e = __expf(p - mx);
                float sm = e;
                sm += __shfl_xor_sync(0xffffffffu, sm, 4);
                sm += __shfl_xor_sync(0xffffffffu, sm, 8);
                sm += __shfl_xor_sync(0xffffffffu, sm, 16);
                const float c = __fdividef(e, sm);
                #pragma unroll
                for (int k = 0; k < 4; k++) sacc[bb][k] = fmaf(c, uh[k], sacc[bb][k]);
            }
        }
    }

    // Flush partial s to global accumulator
    float* sout = &g_s[stage][0];
    #pragma unroll
    for (int bb = 0; bb < 4; bb++) {
        #pragma unroll
        for (int k = 0; k < 4; k++)
            atomicAdd(&sout[(b0 + bb) * 128 + jj * 16 + mq * 4 + k], sacc[bb][k]);
    }
}

// out = squash(s3)
__global__ void final_squash_kernel(float* __restrict__ out)
{
    const int t = blockIdx.x * blockDim.x + threadIdx.x;   // 0..511
    const int b = t >> 3;
    const int j = t & 7;
    const float* sp = &g_s[2][(b * JCAPS + j) * MDIM];
    float sv[MDIM];
    float sn = 0.0f;
    #pragma unroll
    for (int m = 0; m < MDIM; m++) { sv[m] = sp[m]; sn = fmaf(sv[m], sv[m], sn); }
    const float scale = sqrtf(sn) / (1.0f + sn);
    #pragma unroll
    for (int m = 0; m < MDIM; m++) out[(b * JCAPS + j) * MDIM + m] = scale * sv[m];
}

extern "C" void kernel_launch(void* const* d_in, const int* in_sizes, int n_in,
                              void* d_out, int out_size)
{
    const float* x = (const float*)d_in[0];
    const float* W = (const float*)d_in[1];
    // Defensive: identify by element count (x: 64*8192*8 = 4194304, W: 8388608)
    if (n_in >= 2 && in_sizes[0] == 8388608 && in_sizes[1] == 4194304) {
        x = (const float*)d_in[1];
        W = (const float*)d_in[0];
    }

    cudaFuncSetAttribute(route_kernel, cudaFuncAttributeMaxDynamicSharedMemorySize, SMEM_BYTES);

    void* sptr = nullptr;
    cudaGetSymbolAddress(&sptr, g_s);
    cudaMemsetAsync(sptr, 0, sizeof(float) * 3 * BSZ * JCAPS * MDIM);

    for (int st = 0; st < 3; ++st) {
        route_kernel<<<GRID, THREADS, SMEM_BYTES>>>(x, W, st);
    }
    final_squash_kernel<<<16, 32>>>((float*)d_out);
}